// round 2
// baseline (speedup 1.0000x reference)
#include <cuda_runtime.h>
#include <math.h>

// ---------------------------------------------------------------------------
// NCA_3D: y = x + MLP(perc(x)) * floor(mask+0.25);  out = y * (maxpool3(y[:,3]) > 0.1)
// B=8, C=16, S=64, HID=32.  All fp32.
// R2 change: FULLY UNROLL channel loops so all weight accesses are
// immediate-addressed constant loads -> LDCU (floor 1, separate uniform port)
// instead of GPR-addressed LDC (floor 8, half-rate const port).
// Also: pad launch count so ncu (-s 5 -c 1) profiles pass1 next round.
// ---------------------------------------------------------------------------

__constant__ float cW1[32 * 64];
__constant__ float cb1[32];
__constant__ float cW2[16 * 32];

// scratch: alpha plane (B=8 x 64^3)
__device__ float g_alpha[8u << 18];

#define S_CH 600           // per-channel halo slab: 6*10*10
#define TILE_THREADS 256

__global__ __launch_bounds__(TILE_THREADS, 2)
void nca_pass1(const float* __restrict__ x, const float* __restrict__ rmask,
               float* __restrict__ out)
{
    __shared__ float sm[16 * S_CH];   // 38400 B

    int blk = blockIdx.x;
    int w0 = (blk & 7) << 3;
    int h0 = ((blk >> 3) & 7) << 3;
    int d0 = ((blk >> 6) & 15) << 2;
    int b  = blk >> 10;
    const size_t baseB = (size_t)b << 22;   // b * 16 * 64^3

    int tid = threadIdx.x;

    // ---- stage x tile (wrap halo) ----
    for (int i = tid; i < 16 * S_CH; i += TILE_THREADS) {
        int c = i / S_CH;
        int r = i - c * S_CH;
        int dd = r / 100; r -= dd * 100;
        int hh = r / 10;
        int ww = r - hh * 10;
        int gd = (d0 + dd - 1) & 63;
        int gh = (h0 + hh - 1) & 63;
        int gw = (w0 + ww - 1) & 63;
        sm[i] = x[baseB + ((size_t)c << 18) + ((size_t)gd << 12) + (gh << 6) + gw];
    }
    __syncthreads();

    int wx = tid & 7, hy = (tid >> 3) & 7, dz = tid >> 6;
    const int sbase = dz * 100 + hy * 10 + wx;

    float h[32];
#pragma unroll
    for (int o = 0; o < 32; o++) h[o] = cb1[o];

    // FULL unroll: c becomes a compile-time constant -> every cW1 index is an
    // immediate -> LDCU (uniform port, floor 1) instead of LDC (floor 8).
#pragma unroll
    for (int c = 0; c < 16; c++) {
        const float* s = sm + c * S_CH + sbase;
        float v[27];
#pragma unroll
        for (int i = 0; i < 3; i++)
#pragma unroll
            for (int j = 0; j < 3; j++)
#pragma unroll
                for (int k = 0; k < 3; k++)
                    v[(i * 3 + j) * 3 + k] = s[i * 100 + j * 10 + k];

        // a[j][k] = sum_i H[i] v[i][j][k],  H = (1,2,1)
        float a[9];
#pragma unroll
        for (int j = 0; j < 3; j++)
#pragma unroll
            for (int k = 0; k < 3; k++)
                a[j * 3 + k] = fmaf(2.f, v[9 + j * 3 + k], v[j * 3 + k] + v[18 + j * 3 + k]);

        // gx = sum_j H[j] (a[j][2] - a[j][0])
        float gx = fmaf(2.f, a[3 + 2] - a[3 + 0],
                        (a[0 + 2] - a[0 + 0]) + (a[6 + 2] - a[6 + 0]));
        // gy = sum_k H[k] (a[2][k] - a[0][k])
        float gy = fmaf(2.f, a[6 + 1] - a[0 + 1],
                        (a[6 + 0] - a[0 + 0]) + (a[6 + 2] - a[0 + 2]));
        // gz = sum_{j,k} H[j]H[k] (v[2][j][k] - v[0][j][k])
        float r0 = fmaf(2.f, v[18 + 1] - v[1],  (v[18 + 0] - v[0]) + (v[18 + 2] - v[2]));
        float r1 = fmaf(2.f, v[21 + 1] - v[4],  (v[21 + 0] - v[3]) + (v[21 + 2] - v[5]));
        float r2 = fmaf(2.f, v[24 + 1] - v[7],  (v[24 + 0] - v[6]) + (v[24 + 2] - v[8]));
        float gz = fmaf(2.f, r1, r0 + r2);

        float xc = v[13];

#pragma unroll
        for (int o = 0; o < 32; o++) {
            float t = fmaf(cW1[o * 64 + c],      gx, h[o]);
            t       = fmaf(cW1[o * 64 + 16 + c], gy, t);
            t       = fmaf(cW1[o * 64 + 32 + c], gz, t);
            h[o]    = fmaf(cW1[o * 64 + 48 + c], xc, t);
        }
    }

#pragma unroll
    for (int o = 0; o < 32; o++) h[o] = fmaxf(h[o], 0.f);

    int d = d0 + dz, hh2 = h0 + hy, ww2 = w0 + wx;
    size_t sp = ((size_t)d << 12) + (hh2 << 6) + ww2;

    // FULL unroll: cW2 indices become immediates -> LDCU.
#pragma unroll
    for (int c2 = 0; c2 < 16; c2++) {
        float dy = 0.f;
#pragma unroll
        for (int o = 0; o < 32; o++) dy = fmaf(cW2[c2 * 32 + o], h[o], dy);
        float xv = sm[c2 * S_CH + sbase + 111];   // (dz+1)*100 + (hy+1)*10 + (wx+1)
        size_t gi = baseB + ((size_t)c2 << 18) + sp;
        float u  = floorf(rmask[gi] + 0.25f);
        float yv = fmaf(dy, u, xv);
        out[gi] = yv;
        if (c2 == 3) g_alpha[((size_t)b << 18) + sp] = yv;
    }
}

__global__ __launch_bounds__(TILE_THREADS)
void nca_pass2(float* __restrict__ out)
{
    __shared__ float sa[S_CH];

    int blk = blockIdx.x;
    int w0 = (blk & 7) << 3;
    int h0 = ((blk >> 3) & 7) << 3;
    int d0 = ((blk >> 6) & 15) << 2;
    int b  = blk >> 10;
    int tid = threadIdx.x;

    const float* ap = g_alpha + ((size_t)b << 18);
    for (int i = tid; i < S_CH; i += TILE_THREADS) {
        int dd = i / 100; int r = i - dd * 100;
        int hh = r / 10;  int ww = r - hh * 10;
        int gd = d0 + dd - 1, gh = h0 + hh - 1, gw = w0 + ww - 1;
        float val = -3.4e38f;
        if ((unsigned)gd < 64u && (unsigned)gh < 64u && (unsigned)gw < 64u)
            val = ap[((size_t)gd << 12) + (gh << 6) + gw];
        sa[i] = val;
    }
    __syncthreads();

    int wx = tid & 7, hy = (tid >> 3) & 7, dz = tid >> 6;
    const float* s = sa + dz * 100 + hy * 10 + wx;
    float m = -3.4e38f;
#pragma unroll
    for (int i = 0; i < 3; i++)
#pragma unroll
        for (int j = 0; j < 3; j++)
#pragma unroll
            for (int k = 0; k < 3; k++)
                m = fmaxf(m, s[i * 100 + j * 10 + k]);

    if (!(m > 0.1f)) {
        // dead voxel (vanishingly rare): zero all channels
        size_t sp = ((size_t)b << 22) + ((size_t)(d0 + dz) << 12) + ((h0 + hy) << 6) + (w0 + wx);
#pragma unroll
        for (int c = 0; c < 16; c++)
            out[sp + ((size_t)c << 18)] = 0.f;
    }
}

// No-op kernel: pads the per-call kernel-launch count to 5 so ncu's
// "-s 5 -c 1" (skip 5, profile 1) lands on pass1 of the second replay
// instead of always hitting pass2. Costs ~2us each.
__global__ void nca_pad() {}

extern "C" void kernel_launch(void* const* d_in, const int* in_sizes, int n_in,
                              void* d_out, int out_size)
{
    const float* x   = (const float*)d_in[0];
    const float* rm  = (const float*)d_in[1];
    const float* W1  = (const float*)d_in[2];
    const float* b1  = (const float*)d_in[3];
    const float* W2  = (const float*)d_in[4];
    float* out = (float*)d_out;

    int B = in_sizes[0] >> 22;   // elements / (16*64^3)

    cudaMemcpyToSymbolAsync(cW1, W1, 32 * 64 * sizeof(float), 0, cudaMemcpyDeviceToDevice, 0);
    cudaMemcpyToSymbolAsync(cb1, b1, 32 * sizeof(float),       0, cudaMemcpyDeviceToDevice, 0);
    cudaMemcpyToSymbolAsync(cW2, W2, 16 * 32 * sizeof(float),  0, cudaMemcpyDeviceToDevice, 0);

    int blocks = B << 10;   // B * 16(d) * 8(h) * 8(w)
    nca_pass1<<<blocks, TILE_THREADS>>>(x, rm, out);   // launch 1
    nca_pass2<<<blocks, TILE_THREADS>>>(out);          // launch 2
    nca_pad<<<1, 32>>>();                              // launch 3
    nca_pad<<<1, 32>>>();                              // launch 4
    nca_pad<<<1, 32>>>();                              // launch 5 -> next call's pass1 is kernel #6
}

// round 3
// speedup vs baseline: 2.1484x; 2.1484x over previous
#include <cuda_runtime.h>
#include <math.h>

// ---------------------------------------------------------------------------
// NCA_3D  (B=8, C=16, S=64, HID=32, fp32)
// R3: packed f32x2 MLP (2 voxels/thread), weights pre-duplicated (w,w) in
// smem -> broadcast LDS.64 instead of GPR-addressed LDC (floor 8/SMSP).
// Channel loop NOT unrolled (I$-safe). Launch order pads ncu skip-5 onto pass1.
// ---------------------------------------------------------------------------

typedef unsigned long long u64;

__device__ u64 g_w1dup[2048];   // [c][seg][o] dup pairs
__device__ u64 g_w2dup[512];    // [c2][o]     dup pairs
__device__ u64 g_b1dup[32];
__device__ float g_alpha[8u << 18];

__device__ __forceinline__ u64 pack2(float lo, float hi) {
    u64 r; asm("mov.b64 %0, {%1, %2};" : "=l"(r) : "f"(lo), "f"(hi)); return r;
}
__device__ __forceinline__ void unpack2(u64 p, float& lo, float& hi) {
    asm("mov.b64 {%0, %1}, %2;" : "=f"(lo), "=f"(hi) : "l"(p));
}
__device__ __forceinline__ u64 ffma2(u64 a, u64 b, u64 c) {
    u64 d; asm("fma.rn.f32x2 %0, %1, %2, %3;" : "=l"(d) : "l"(a), "l"(b), "l"(c)); return d;
}
__device__ __forceinline__ u64 fadd2(u64 a, u64 b) {
    u64 d; asm("add.rn.f32x2 %0, %1, %2;" : "=l"(d) : "l"(a), "l"(b)); return d;
}

#define S_CH 600            // 6*10*10 halo slab per channel
#define P1_THREADS 128

// smem carve offsets (bytes)
#define OFF_W1  38400
#define OFF_W2  (38400 + 16384)
#define OFF_B1  (38400 + 16384 + 4096)
#define SMEM_P1 (38400 + 16384 + 4096 + 256)   // 59136

__global__ void nca_prep(const float* __restrict__ W1, const float* __restrict__ b1,
                         const float* __restrict__ W2)
{
    int t = threadIdx.x;
    for (int i = t; i < 2048; i += 256) {
        int o = i & 31, seg = (i >> 5) & 3, c = i >> 7;
        float w = W1[o * 64 + seg * 16 + c];
        g_w1dup[i] = pack2(w, w);
    }
    for (int i = t; i < 512; i += 256) { float w = W2[i]; g_w2dup[i] = pack2(w, w); }
    if (t < 32) { float w = b1[t]; g_b1dup[t] = pack2(w, w); }
}

__global__ __launch_bounds__(P1_THREADS, 2)
void nca_pass1(const float* __restrict__ x, const float* __restrict__ rmask,
               float* __restrict__ out)
{
    extern __shared__ char smraw[];
    float* sm  = (float*)smraw;                 // 16 * 600 floats
    u64*   sW1 = (u64*)(smraw + OFF_W1);        // 2048 pairs
    u64*   sW2 = (u64*)(smraw + OFF_W2);        // 512 pairs
    u64*   sB1 = (u64*)(smraw + OFF_B1);        // 32 pairs

    int blk = blockIdx.x;
    int w0t = (blk & 7) << 3;
    int h0  = ((blk >> 3) & 7) << 3;
    int d0  = ((blk >> 6) & 15) << 2;
    int b   = blk >> 10;
    const size_t baseB = (size_t)b << 22;
    int tid = threadIdx.x;

    // ---- stage weights ----
    for (int i = tid; i < 2048; i += P1_THREADS) sW1[i] = g_w1dup[i];
    for (int i = tid; i < 512;  i += P1_THREADS) sW2[i] = g_w2dup[i];
    if (tid < 32) sB1[tid] = g_b1dup[tid];

    // ---- stage x tile (wrap halo) ----
    for (int i = tid; i < 16 * S_CH; i += P1_THREADS) {
        int c = i / S_CH;
        int r = i - c * S_CH;
        int dd = r / 100; r -= dd * 100;
        int hh = r / 10;
        int ww = r - hh * 10;
        int gd = (d0 + dd - 1) & 63;
        int gh = (h0 + hh - 1) & 63;
        int gw = (w0t + ww - 1) & 63;
        sm[i] = x[baseB + ((size_t)c << 18) + ((size_t)gd << 12) + (gh << 6) + gw];
    }
    __syncthreads();

    // thread -> voxel pair (w0, w0+1)
    int wp = tid & 3;          int w0 = wp << 1;
    int hy = (tid >> 2) & 7;   int dz = tid >> 5;      // dz 0..3
    const int sb = dz * 100 + hy * 10 + w0;

    u64 h2[32];
#pragma unroll
    for (int o = 0; o < 32; o++) h2[o] = sB1[o];

#pragma unroll 1
    for (int c = 0; c < 16; c++) {
        const float* s = sm + c * S_CH + sb;

        // taps: 3x3x4 columns (k=0..3 -> halo W = w0+k)
        float v[36];
#pragma unroll
        for (int i = 0; i < 3; i++)
#pragma unroll
            for (int j = 0; j < 3; j++)
#pragma unroll
                for (int k = 0; k < 4; k++)
                    v[(i * 3 + j) * 4 + k] = s[i * 100 + j * 10 + k];

        // a[j][k] = H-conv over d  (H = 1,2,1)
        float a[12];
#pragma unroll
        for (int j = 0; j < 3; j++)
#pragma unroll
            for (int k = 0; k < 4; k++)
                a[j * 4 + k] = fmaf(2.f, v[(3 + j) * 4 + k], v[j * 4 + k] + v[(6 + j) * 4 + k]);

        float gx0 = fmaf(2.f, a[4 + 2] - a[4 + 0], (a[2] - a[0]) + (a[8 + 2] - a[8 + 0]));
        float gx1 = fmaf(2.f, a[4 + 3] - a[4 + 1], (a[3] - a[1]) + (a[8 + 3] - a[8 + 1]));

        float e0 = a[8] - a[0], e1 = a[9] - a[1], e2 = a[10] - a[2], e3 = a[11] - a[3];
        float gy0 = fmaf(2.f, e1, e0 + e2);
        float gy1 = fmaf(2.f, e2, e1 + e3);

        float rr[4];
#pragma unroll
        for (int k = 0; k < 4; k++) {
            float g0 = v[24 + k] - v[k];            // (i=2,j=0) - (i=0,j=0)
            float g1 = v[28 + k] - v[4 + k];        // j=1
            float g2 = v[32 + k] - v[8 + k];        // j=2
            rr[k] = fmaf(2.f, g1, g0 + g2);
        }
        float gz0 = fmaf(2.f, rr[1], rr[0] + rr[2]);
        float gz1 = fmaf(2.f, rr[2], rr[1] + rr[3]);

        float xc0 = v[16 + 1], xc1 = v[16 + 2];     // (i=1,j=1,k=1/2)

        u64 gxp = pack2(gx0, gx1), gyp = pack2(gy0, gy1);
        u64 gzp = pack2(gz0, gz1), xcp = pack2(xc0, xc1);

        const u64* w = sW1 + c * 128;
#pragma unroll
        for (int o = 0; o < 32; o++) {
            u64 t = ffma2(gxp, w[o],      h2[o]);
            t     = ffma2(gyp, w[32 + o], t);
            t     = ffma2(gzp, w[64 + o], t);
            h2[o] = ffma2(xcp, w[96 + o], t);
        }
    }

    // relu (unpack/max/repack)
#pragma unroll
    for (int o = 0; o < 32; o++) {
        float lo, hi; unpack2(h2[o], lo, hi);
        h2[o] = pack2(fmaxf(lo, 0.f), fmaxf(hi, 0.f));
    }

    int d = d0 + dz, hg = h0 + hy, wg = w0t + w0;
    size_t sp = ((size_t)d << 12) + (hg << 6) + wg;

#pragma unroll 1
    for (int c2 = 0; c2 < 16; c2++) {
        const u64* w2 = sW2 + c2 * 32;
        u64 A = 0ull, B2 = 0ull, C2 = 0ull, D2 = 0ull;   // 0 bits == (0.f,0.f)
#pragma unroll
        for (int o = 0; o < 32; o += 4) {
            A  = ffma2(h2[o],     w2[o],     A);
            B2 = ffma2(h2[o + 1], w2[o + 1], B2);
            C2 = ffma2(h2[o + 2], w2[o + 2], C2);
            D2 = ffma2(h2[o + 3], w2[o + 3], D2);
        }
        u64 dyp = fadd2(fadd2(A, B2), fadd2(C2, D2));
        float dy0, dy1; unpack2(dyp, dy0, dy1);

        size_t gi = baseB + ((size_t)c2 << 18) + sp;
        float2 rm2 = *(const float2*)(rmask + gi);
        float u0 = floorf(rm2.x + 0.25f);
        float u1 = floorf(rm2.y + 0.25f);
        float xv0 = sm[c2 * S_CH + sb + 111];
        float xv1 = sm[c2 * S_CH + sb + 112];
        float y0 = fmaf(dy0, u0, xv0);
        float y1 = fmaf(dy1, u1, xv1);
        *(float2*)(out + gi) = make_float2(y0, y1);
        if (c2 == 3) *(float2*)(g_alpha + ((size_t)b << 18) + sp) = make_float2(y0, y1);
    }
}

__global__ __launch_bounds__(256)
void nca_pass2(float* __restrict__ out)
{
    __shared__ float sa[S_CH];

    int blk = blockIdx.x;
    int w0 = (blk & 7) << 3;
    int h0 = ((blk >> 3) & 7) << 3;
    int d0 = ((blk >> 6) & 15) << 2;
    int b  = blk >> 10;
    int tid = threadIdx.x;

    const float* ap = g_alpha + ((size_t)b << 18);
    for (int i = tid; i < S_CH; i += 256) {
        int dd = i / 100; int r = i - dd * 100;
        int hh = r / 10;  int ww = r - hh * 10;
        int gd = d0 + dd - 1, gh = h0 + hh - 1, gw = w0 + ww - 1;
        float val = -3.4e38f;
        if ((unsigned)gd < 64u && (unsigned)gh < 64u && (unsigned)gw < 64u)
            val = ap[((size_t)gd << 12) + (gh << 6) + gw];
        sa[i] = val;
    }
    __syncthreads();

    int wx = tid & 7, hy = (tid >> 3) & 7, dz = tid >> 6;
    const float* s = sa + dz * 100 + hy * 10 + wx;
    float m = -3.4e38f;
#pragma unroll
    for (int i = 0; i < 3; i++)
#pragma unroll
        for (int j = 0; j < 3; j++)
#pragma unroll
            for (int k = 0; k < 3; k++)
                m = fmaxf(m, s[i * 100 + j * 10 + k]);

    if (!(m > 0.1f)) {
        size_t sp = ((size_t)b << 22) + ((size_t)(d0 + dz) << 12) + ((h0 + hy) << 6) + (w0 + wx);
#pragma unroll
        for (int c = 0; c < 16; c++)
            out[sp + ((size_t)c << 18)] = 0.f;
    }
}

__global__ void nca_pad() {}

extern "C" void kernel_launch(void* const* d_in, const int* in_sizes, int n_in,
                              void* d_out, int out_size)
{
    const float* x   = (const float*)d_in[0];
    const float* rm  = (const float*)d_in[1];
    const float* W1  = (const float*)d_in[2];
    const float* b1  = (const float*)d_in[3];
    const float* W2  = (const float*)d_in[4];
    float* out = (float*)d_out;

    int B = in_sizes[0] >> 22;

    static int smem_set = 0;
    if (!smem_set) {
        cudaFuncSetAttribute(nca_pass1, cudaFuncAttributeMaxDynamicSharedMemorySize, SMEM_P1);
        smem_set = 1;
    }

    int blocks = B << 10;
    // order: [prep, pass1, pass2, pad] -> launch #6 overall = pass1 (ncu -s 5 -c 1)
    nca_prep<<<1, 256>>>(W1, b1, W2);
    nca_pass1<<<blocks, P1_THREADS, SMEM_P1>>>(x, rm, out);
    nca_pass2<<<blocks, 256>>>(out);
    nca_pad<<<1, 32>>>();
}

// round 4
// speedup vs baseline: 2.1970x; 1.0226x over previous
#include <cuda_runtime.h>
#include <math.h>

// ---------------------------------------------------------------------------
// NCA_3D  (B=8, C=16, S=64, HID=32, fp32)
// R4: occupancy 2->3 blocks/SM (launch_bounds(128,3)); weights re-laid-out for
// LDS.128 loads; stencil taps loaded as float2. 3 launches/call so the ncu
// profile (8th launch overall) lands on pass1.
// ---------------------------------------------------------------------------

typedef unsigned long long u64;

__device__ u64 g_w1dup[2048];   // [c][o][seg]  dup pairs, 32B per (c,o)
__device__ u64 g_w2dup[512];    // [c2][o]      dup pairs
__device__ u64 g_b1dup[32];
__device__ float g_alpha[8u << 18];

__device__ __forceinline__ u64 pack2(float lo, float hi) {
    u64 r; asm("mov.b64 %0, {%1, %2};" : "=l"(r) : "f"(lo), "f"(hi)); return r;
}
__device__ __forceinline__ void unpack2(u64 p, float& lo, float& hi) {
    asm("mov.b64 {%0, %1}, %2;" : "=f"(lo), "=f"(hi) : "l"(p));
}
__device__ __forceinline__ u64 ffma2(u64 a, u64 b, u64 c) {
    u64 d; asm("fma.rn.f32x2 %0, %1, %2, %3;" : "=l"(d) : "l"(a), "l"(b), "l"(c)); return d;
}
__device__ __forceinline__ u64 fadd2(u64 a, u64 b) {
    u64 d; asm("add.rn.f32x2 %0, %1, %2;" : "=l"(d) : "l"(a), "l"(b)); return d;
}

#define S_CH 600            // 6*10*10 halo slab per channel
#define P1_THREADS 128

// smem carve offsets (bytes)
#define OFF_W1  38400
#define OFF_W2  (38400 + 16384)
#define OFF_B1  (38400 + 16384 + 4096)
#define SMEM_P1 (38400 + 16384 + 4096 + 256)   // 59136

__global__ void nca_prep(const float* __restrict__ W1, const float* __restrict__ b1,
                         const float* __restrict__ W2)
{
    int t = threadIdx.x;
    // layout: [c][o][seg] -> 4 consecutive u64 per (c,o) for LDS.128
    for (int i = t; i < 2048; i += 256) {
        int seg = i & 3, o = (i >> 2) & 31, c = i >> 7;
        float w = W1[o * 64 + seg * 16 + c];
        g_w1dup[i] = pack2(w, w);
    }
    for (int i = t; i < 512; i += 256) { float w = W2[i]; g_w2dup[i] = pack2(w, w); }
    if (t < 32) { float w = b1[t]; g_b1dup[t] = pack2(w, w); }
}

__global__ __launch_bounds__(P1_THREADS, 3)
void nca_pass1(const float* __restrict__ x, const float* __restrict__ rmask,
               float* __restrict__ out)
{
    extern __shared__ char smraw[];
    float* sm  = (float*)smraw;                 // 16 * 600 floats
    u64*   sW1 = (u64*)(smraw + OFF_W1);        // 2048 pairs (16B-aligned groups of 4)
    u64*   sW2 = (u64*)(smraw + OFF_W2);        // 512 pairs
    u64*   sB1 = (u64*)(smraw + OFF_B1);        // 32 pairs

    int blk = blockIdx.x;
    int w0t = (blk & 7) << 3;
    int h0  = ((blk >> 3) & 7) << 3;
    int d0  = ((blk >> 6) & 15) << 2;
    int b   = blk >> 10;
    const size_t baseB = (size_t)b << 22;
    int tid = threadIdx.x;

    // ---- stage weights ----
    {
        const u64* g1 = g_w1dup;
#pragma unroll 4
        for (int i = tid; i < 2048; i += P1_THREADS) sW1[i] = g1[i];
        for (int i = tid; i < 512;  i += P1_THREADS) sW2[i] = g_w2dup[i];
        if (tid < 32) sB1[tid] = g_b1dup[tid];
    }

    // ---- stage x tile (wrap halo) ----
    for (int i = tid; i < 16 * S_CH; i += P1_THREADS) {
        int c = i / S_CH;
        int r = i - c * S_CH;
        int dd = r / 100; r -= dd * 100;
        int hh = r / 10;
        int ww = r - hh * 10;
        int gd = (d0 + dd - 1) & 63;
        int gh = (h0 + hh - 1) & 63;
        int gw = (w0t + ww - 1) & 63;
        sm[i] = x[baseB + ((size_t)c << 18) + ((size_t)gd << 12) + (gh << 6) + gw];
    }
    __syncthreads();

    // thread -> voxel pair (w0, w0+1)
    int wp = tid & 3;          int w0 = wp << 1;
    int hy = (tid >> 2) & 7;   int dz = tid >> 5;      // dz 0..3
    const int sb = dz * 100 + hy * 10 + w0;            // even

    u64 h2[32];
#pragma unroll
    for (int o = 0; o < 32; o++) h2[o] = sB1[o];

#pragma unroll 1
    for (int c = 0; c < 16; c++) {
        const float2* s2 = (const float2*)(sm + c * S_CH + sb);   // 8B-aligned

        // taps: 3x3x4 columns via float2 loads
        float v[36];
#pragma unroll
        for (int i = 0; i < 3; i++)
#pragma unroll
            for (int j = 0; j < 3; j++) {
                int half = (i * 100 + j * 10) >> 1;
                float2 p0 = s2[half];
                float2 p1 = s2[half + 1];
                int o4 = (i * 3 + j) * 4;
                v[o4 + 0] = p0.x; v[o4 + 1] = p0.y;
                v[o4 + 2] = p1.x; v[o4 + 3] = p1.y;
            }

        // a[j][k] = H-conv over d  (H = 1,2,1)
        float a[12];
#pragma unroll
        for (int j = 0; j < 3; j++)
#pragma unroll
            for (int k = 0; k < 4; k++)
                a[j * 4 + k] = fmaf(2.f, v[(3 + j) * 4 + k], v[j * 4 + k] + v[(6 + j) * 4 + k]);

        float gx0 = fmaf(2.f, a[4 + 2] - a[4 + 0], (a[2] - a[0]) + (a[8 + 2] - a[8 + 0]));
        float gx1 = fmaf(2.f, a[4 + 3] - a[4 + 1], (a[3] - a[1]) + (a[8 + 3] - a[8 + 1]));

        float e0 = a[8] - a[0], e1 = a[9] - a[1], e2 = a[10] - a[2], e3 = a[11] - a[3];
        float gy0 = fmaf(2.f, e1, e0 + e2);
        float gy1 = fmaf(2.f, e2, e1 + e3);

        float rr[4];
#pragma unroll
        for (int k = 0; k < 4; k++) {
            float g0 = v[24 + k] - v[k];
            float g1 = v[28 + k] - v[4 + k];
            float g2 = v[32 + k] - v[8 + k];
            rr[k] = fmaf(2.f, g1, g0 + g2);
        }
        float gz0 = fmaf(2.f, rr[1], rr[0] + rr[2]);
        float gz1 = fmaf(2.f, rr[2], rr[1] + rr[3]);

        float xc0 = v[16 + 1], xc1 = v[16 + 2];

        u64 gxp = pack2(gx0, gx1), gyp = pack2(gy0, gy1);
        u64 gzp = pack2(gz0, gz1), xcp = pack2(xc0, xc1);

        // weights: 4 u64 per (c,o), contiguous -> 2x LDS.128 per o
        const ulonglong2* w = (const ulonglong2*)(sW1 + c * 128);
#pragma unroll
        for (int o = 0; o < 32; o++) {
            ulonglong2 wa = w[2 * o];       // (gx_w, gy_w)
            ulonglong2 wb = w[2 * o + 1];   // (gz_w, xc_w)
            u64 t = ffma2(gxp, wa.x, h2[o]);
            t     = ffma2(gyp, wa.y, t);
            t     = ffma2(gzp, wb.x, t);
            h2[o] = ffma2(xcp, wb.y, t);
        }
    }

    // relu
#pragma unroll
    for (int o = 0; o < 32; o++) {
        float lo, hi; unpack2(h2[o], lo, hi);
        h2[o] = pack2(fmaxf(lo, 0.f), fmaxf(hi, 0.f));
    }

    int d = d0 + dz, hg = h0 + hy, wg = w0t + w0;
    size_t sp = ((size_t)d << 12) + (hg << 6) + wg;

#pragma unroll 1
    for (int c2 = 0; c2 < 16; c2++) {
        const ulonglong2* w2 = (const ulonglong2*)(sW2 + c2 * 32);
        u64 A = 0ull, B2 = 0ull, C2 = 0ull, D2 = 0ull;
#pragma unroll
        for (int q = 0; q < 16; q += 2) {
            ulonglong2 p0 = w2[q];
            ulonglong2 p1 = w2[q + 1];
            A  = ffma2(h2[2 * q],     p0.x, A);
            B2 = ffma2(h2[2 * q + 1], p0.y, B2);
            C2 = ffma2(h2[2 * q + 2], p1.x, C2);
            D2 = ffma2(h2[2 * q + 3], p1.y, D2);
        }
        u64 dyp = fadd2(fadd2(A, B2), fadd2(C2, D2));
        float dy0, dy1; unpack2(dyp, dy0, dy1);

        size_t gi = baseB + ((size_t)c2 << 18) + sp;
        float2 rm2 = *(const float2*)(rmask + gi);
        float u0 = floorf(rm2.x + 0.25f);
        float u1 = floorf(rm2.y + 0.25f);
        float xv0 = sm[c2 * S_CH + sb + 111];
        float xv1 = sm[c2 * S_CH + sb + 112];
        float y0 = fmaf(dy0, u0, xv0);
        float y1 = fmaf(dy1, u1, xv1);
        *(float2*)(out + gi) = make_float2(y0, y1);
        if (c2 == 3) *(float2*)(g_alpha + ((size_t)b << 18) + sp) = make_float2(y0, y1);
    }
}

__global__ __launch_bounds__(256)
void nca_pass2(float* __restrict__ out)
{
    __shared__ float sa[S_CH];

    int blk = blockIdx.x;
    int w0 = (blk & 7) << 3;
    int h0 = ((blk >> 3) & 7) << 3;
    int d0 = ((blk >> 6) & 15) << 2;
    int b  = blk >> 10;
    int tid = threadIdx.x;

    const float* ap = g_alpha + ((size_t)b << 18);
    for (int i = tid; i < S_CH; i += 256) {
        int dd = i / 100; int r = i - dd * 100;
        int hh = r / 10;  int ww = r - hh * 10;
        int gd = d0 + dd - 1, gh = h0 + hh - 1, gw = w0 + ww - 1;
        float val = -3.4e38f;
        if ((unsigned)gd < 64u && (unsigned)gh < 64u && (unsigned)gw < 64u)
            val = ap[((size_t)gd << 12) + (gh << 6) + gw];
        sa[i] = val;
    }
    __syncthreads();

    int wx = tid & 7, hy = (tid >> 3) & 7, dz = tid >> 6;
    const float* s = sa + dz * 100 + hy * 10 + wx;
    float m = -3.4e38f;
#pragma unroll
    for (int i = 0; i < 3; i++)
#pragma unroll
        for (int j = 0; j < 3; j++)
#pragma unroll
            for (int k = 0; k < 3; k++)
                m = fmaxf(m, s[i * 100 + j * 10 + k]);

    if (!(m > 0.1f)) {
        size_t sp = ((size_t)b << 22) + ((size_t)(d0 + dz) << 12) + ((h0 + hy) << 6) + (w0 + wx);
#pragma unroll
        for (int c = 0; c < 16; c++)
            out[sp + ((size_t)c << 18)] = 0.f;
    }
}

extern "C" void kernel_launch(void* const* d_in, const int* in_sizes, int n_in,
                              void* d_out, int out_size)
{
    const float* x   = (const float*)d_in[0];
    const float* rm  = (const float*)d_in[1];
    const float* W1  = (const float*)d_in[2];
    const float* b1  = (const float*)d_in[3];
    const float* W2  = (const float*)d_in[4];
    float* out = (float*)d_out;

    int B = in_sizes[0] >> 22;

    static int smem_set = 0;
    if (!smem_set) {
        cudaFuncSetAttribute(nca_pass1, cudaFuncAttributeMaxDynamicSharedMemorySize, SMEM_P1);
        smem_set = 1;
    }

    int blocks = B << 10;
    // exactly 3 launches/call -> 8th launch overall = call3's pass1 (ncu target)
    nca_prep<<<1, 256>>>(W1, b1, W2);
    nca_pass1<<<blocks, P1_THREADS, SMEM_P1>>>(x, rm, out);
    nca_pass2<<<blocks, 256>>>(out);
}

// round 6
// speedup vs baseline: 3.3952x; 1.5454x over previous
#include <cuda_runtime.h>
#include <cuda_bf16.h>
#include <math.h>

// ---------------------------------------------------------------------------
// NCA_3D  (B=8, C=16, S=64, HID=32, fp32)
// R6: warp-level HMMA (mma.sync m16n8k16 bf16) — tcgen05 unavailable (harness
// targets sm_103, not sm_103a).
//   per CTA: 128 voxels (8w x 4h x 4d), 4 warps, 1 warp = 32 voxels (M=32).
//   Sobel fp32 -> bf16 A [128 x 64] smem (pitch 144B, conflict-free frags)
//   GEMM1: M32 N32 K64 (32 mma) -> bias+relu in C frags
//   C1 frag -> A2 frag: register-only repack
//   GEMM2: M32 N16 K32 (8 mma) -> dy frags -> epilogue
// ---------------------------------------------------------------------------

typedef unsigned int u32;

__device__ u32  g_w1t[32 * 64 / 2];    // bf16 [n=32][k=64], k = 4c+seg
__device__ u32  g_w2t[16 * 32 / 2];    // bf16 [n=16][k=32]  (= W2 verbatim)
__device__ float g_alpha[8u << 18];

__device__ __forceinline__ u32 cvt_bf16x2(float hi, float lo) {
    u32 r; asm("cvt.rn.bf16x2.f32 %0, %1, %2;" : "=r"(r) : "f"(hi), "f"(lo)); return r;
}
__device__ __forceinline__ void mma16816(float* d, const u32* a, const u32* b) {
    asm("mma.sync.aligned.m16n8k16.row.col.f32.bf16.bf16.f32 "
        "{%0,%1,%2,%3}, {%4,%5,%6,%7}, {%8,%9}, {%0,%1,%2,%3};"
        : "+f"(d[0]), "+f"(d[1]), "+f"(d[2]), "+f"(d[3])
        : "r"(a[0]), "r"(a[1]), "r"(a[2]), "r"(a[3]), "r"(b[0]), "r"(b[1]));
}

#define S_SLAB 360            // 6d x 6h x 10w per channel
#define A_PITCH_U32 36        // 144 B row pitch
// smem byte offsets
#define OFF_SLAB 0
#define OFF_A    23040        // 128 * 144 = 18432
#define OFF_W1   41472        // 4096
#define OFF_W2   45568        // 1024
#define OFF_BIAS 46592        // 128
#define SMEM_P1  46720

// ---------------------------------------------------------------------------
__global__ void nca_prep(const float* __restrict__ W1, const float* __restrict__ W2)
{
    int t = threadIdx.x;
    __nv_bfloat16* w1 = (__nv_bfloat16*)g_w1t;
    for (int i = t; i < 32 * 64; i += 256) {
        int n = i >> 6, k = i & 63;
        w1[i] = __float2bfloat16(W1[n * 64 + (k & 3) * 16 + (k >> 2)]);
    }
    __nv_bfloat16* w2 = (__nv_bfloat16*)g_w2t;
    for (int i = t; i < 16 * 32; i += 256)
        w2[i] = __float2bfloat16(W2[i]);
}

// ---------------------------------------------------------------------------
__global__ __launch_bounds__(128, 4)
void nca_pass1(const float* __restrict__ x, const float* __restrict__ rmask,
               const float* __restrict__ b1, float* __restrict__ out)
{
    extern __shared__ char smraw[];
    float* slab = (float*)(smraw + OFF_SLAB);
    u32*   Au   = (u32*)(smraw + OFF_A);
    u32*   w1u  = (u32*)(smraw + OFF_W1);
    u32*   w2u  = (u32*)(smraw + OFF_W2);
    float* sB   = (float*)(smraw + OFF_BIAS);

    int tid  = threadIdx.x;
    int warp = tid >> 5;
    int lane = tid & 31;
    int g = lane >> 2, c = lane & 3;

    int blk = blockIdx.x;
    int w0 = (blk & 7) << 3;
    int h0 = ((blk >> 3) & 15) << 2;
    int d0 = ((blk >> 7) & 15) << 2;
    int b  = blk >> 11;
    const size_t baseB = (size_t)b << 22;

    // ---- stage x slab (wrap halo) ----
    for (int i = tid; i < 16 * S_SLAB; i += 128) {
        int ch = i / S_SLAB;
        int r = i - ch * S_SLAB;
        int sd = r / 60; r -= sd * 60;
        int sh = r / 10;
        int sw = r - sh * 10;
        int gd = (d0 + sd - 1) & 63;
        int gh = (h0 + sh - 1) & 63;
        int gw = (w0 + sw - 1) & 63;
        slab[i] = x[baseB + ((size_t)ch << 18) + ((size_t)gd << 12) + (gh << 6) + gw];
    }
    // ---- stage weights + bias ----
    {
        uint4* d1 = (uint4*)w1u; const uint4* s1 = (const uint4*)g_w1t;
        for (int i = tid; i < 256; i += 128) d1[i] = s1[i];
        uint4* d2 = (uint4*)w2u; const uint4* s2 = (const uint4*)g_w2t;
        if (tid < 64) d2[tid] = s2[tid];
        if (tid < 32) sB[tid] = b1[tid];
    }
    __syncthreads();

    // ---- Sobel -> bf16 A rows (row = tid, k = 4c+seg) ----
    {
        int vw = tid & 7, vh = (tid >> 3) & 3, vd = tid >> 5;
        uint2* Arow = (uint2*)((char*)Au + tid * 144);
#pragma unroll 1
        for (int ch = 0; ch < 16; ch++) {
            const float* s = slab + ch * S_SLAB + vd * 60 + vh * 10 + vw;
            float v[27];
#pragma unroll
            for (int i = 0; i < 3; i++)
#pragma unroll
                for (int j = 0; j < 3; j++)
#pragma unroll
                    for (int k = 0; k < 3; k++)
                        v[(i * 3 + j) * 3 + k] = s[i * 60 + j * 10 + k];

            float a[9];
#pragma unroll
            for (int j = 0; j < 3; j++)
#pragma unroll
                for (int k = 0; k < 3; k++)
                    a[j * 3 + k] = fmaf(2.f, v[9 + j * 3 + k], v[j * 3 + k] + v[18 + j * 3 + k]);

            float gx = fmaf(2.f, a[5] - a[3], (a[2] - a[0]) + (a[8] - a[6]));
            float gy = fmaf(2.f, a[7] - a[1], (a[6] - a[0]) + (a[8] - a[2]));
            float r0 = fmaf(2.f, v[19] - v[1], (v[18] - v[0]) + (v[20] - v[2]));
            float r1 = fmaf(2.f, v[22] - v[4], (v[21] - v[3]) + (v[23] - v[5]));
            float r2 = fmaf(2.f, v[25] - v[7], (v[24] - v[6]) + (v[26] - v[8]));
            float gz = fmaf(2.f, r1, r0 + r2);
            float xc = v[13];

            uint2 pk;
            pk.x = cvt_bf16x2(gy, gx);   // k=4c, 4c+1
            pk.y = cvt_bf16x2(xc, gz);   // k=4c+2, 4c+3
            Arow[ch] = pk;
        }
    }
    __syncthreads();

    // ---- B fragments (one-time) ----
    u32 B1f[4][4][2];   // [nt][kt]
#pragma unroll
    for (int nt = 0; nt < 4; nt++)
#pragma unroll
        for (int kt = 0; kt < 4; kt++) {
            int idx = (g + 8 * nt) * 32 + 8 * kt + c;
            B1f[nt][kt][0] = w1u[idx];
            B1f[nt][kt][1] = w1u[idx + 4];
        }
    u32 B2f[2][2][2];   // [nt2][kt2]
#pragma unroll
    for (int nt = 0; nt < 2; nt++)
#pragma unroll
        for (int kt = 0; kt < 2; kt++) {
            int idx = (g + 8 * nt) * 16 + 8 * kt + c;
            B2f[nt][kt][0] = w2u[idx];
            B2f[nt][kt][1] = w2u[idx + 4];
        }

    // ---- GEMM1: M32 N32 K64 ----
    float C1[2][4][4];
#pragma unroll
    for (int mt = 0; mt < 2; mt++)
#pragma unroll
        for (int nt = 0; nt < 4; nt++)
#pragma unroll
            for (int q = 0; q < 4; q++) C1[mt][nt][q] = 0.f;

#pragma unroll
    for (int kt = 0; kt < 4; kt++) {
#pragma unroll
        for (int mt = 0; mt < 2; mt++) {
            int r = warp * 32 + mt * 16 + g;
            int base = r * A_PITCH_U32 + 8 * kt + c;
            u32 a[4];
            a[0] = Au[base];
            a[1] = Au[base + 8 * A_PITCH_U32];
            a[2] = Au[base + 4];
            a[3] = Au[base + 8 * A_PITCH_U32 + 4];
#pragma unroll
            for (int nt = 0; nt < 4; nt++)
                mma16816(C1[mt][nt], a, B1f[nt][kt]);
        }
    }

    // ---- bias + relu ----
#pragma unroll
    for (int nt = 0; nt < 4; nt++) {
        float blo = sB[2 * c + 8 * nt];
        float bhi = sB[2 * c + 1 + 8 * nt];
#pragma unroll
        for (int mt = 0; mt < 2; mt++) {
            C1[mt][nt][0] = fmaxf(C1[mt][nt][0] + blo, 0.f);
            C1[mt][nt][1] = fmaxf(C1[mt][nt][1] + bhi, 0.f);
            C1[mt][nt][2] = fmaxf(C1[mt][nt][2] + blo, 0.f);
            C1[mt][nt][3] = fmaxf(C1[mt][nt][3] + bhi, 0.f);
        }
    }

    // ---- repack C1 frags -> A2 frags (registers only) ----
    u32 A2f[2][2][4];   // [mt][kt2]
#pragma unroll
    for (int mt = 0; mt < 2; mt++)
#pragma unroll
        for (int kt = 0; kt < 2; kt++) {
            A2f[mt][kt][0] = cvt_bf16x2(C1[mt][2 * kt][1],     C1[mt][2 * kt][0]);
            A2f[mt][kt][1] = cvt_bf16x2(C1[mt][2 * kt][3],     C1[mt][2 * kt][2]);
            A2f[mt][kt][2] = cvt_bf16x2(C1[mt][2 * kt + 1][1], C1[mt][2 * kt + 1][0]);
            A2f[mt][kt][3] = cvt_bf16x2(C1[mt][2 * kt + 1][3], C1[mt][2 * kt + 1][2]);
        }

    // ---- GEMM2: M32 N16 K32 ----
    float D2[2][2][4];
#pragma unroll
    for (int mt = 0; mt < 2; mt++)
#pragma unroll
        for (int nt = 0; nt < 2; nt++)
#pragma unroll
            for (int q = 0; q < 4; q++) D2[mt][nt][q] = 0.f;
#pragma unroll
    for (int kt = 0; kt < 2; kt++)
#pragma unroll
        for (int mt = 0; mt < 2; mt++)
#pragma unroll
            for (int nt = 0; nt < 2; nt++)
                mma16816(D2[mt][nt], A2f[mt][kt], B2f[nt][kt]);

    // ---- epilogue: thread owns voxels (vd=warp, vh=0..3, vw=g), ch {2c,2c+1,2c+8,2c+9}
    {
        int vw = g, vd = warp;
        int d = d0 + vd, ww = w0 + vw;
#pragma unroll
        for (int mt = 0; mt < 2; mt++)
#pragma unroll
            for (int h2 = 0; h2 < 2; h2++) {
                int vh = mt * 2 + h2;
                int hh = h0 + vh;
                size_t sp = ((size_t)d << 12) + (hh << 6) + ww;
                int sctr = (vd + 1) * 60 + (vh + 1) * 10 + (vw + 1);
#pragma unroll
                for (int nt = 0; nt < 2; nt++)
#pragma unroll
                    for (int lh = 0; lh < 2; lh++) {
                        int ch = 2 * c + lh + 8 * nt;
                        float dy = D2[mt][nt][h2 * 2 + lh];
                        float xv = slab[ch * S_SLAB + sctr];
                        size_t gi = baseB + ((size_t)ch << 18) + sp;
                        float u = floorf(rmask[gi] + 0.25f);
                        float y = fmaf(dy, u, xv);
                        out[gi] = y;
                        if (ch == 3) g_alpha[((size_t)b << 18) + sp] = y;
                    }
            }
    }
}

// ---------------------------------------------------------------------------
__global__ __launch_bounds__(256)
void nca_pass2(float* __restrict__ out)
{
    __shared__ float sa[600];

    int blk = blockIdx.x;
    int w0 = (blk & 7) << 3;
    int h0 = ((blk >> 3) & 7) << 3;
    int d0 = ((blk >> 6) & 15) << 2;
    int b  = blk >> 10;
    int tid = threadIdx.x;

    const float* ap = g_alpha + ((size_t)b << 18);
    for (int i = tid; i < 600; i += 256) {
        int dd = i / 100; int r = i - dd * 100;
        int hh = r / 10;  int ww = r - hh * 10;
        int gd = d0 + dd - 1, gh = h0 + hh - 1, gw = w0 + ww - 1;
        float val = -3.4e38f;
        if ((unsigned)gd < 64u && (unsigned)gh < 64u && (unsigned)gw < 64u)
            val = ap[((size_t)gd << 12) + (gh << 6) + gw];
        sa[i] = val;
    }
    __syncthreads();

    int wx = tid & 7, hy = (tid >> 3) & 7, dz = tid >> 6;
    const float* s = sa + dz * 100 + hy * 10 + wx;
    float m = -3.4e38f;
#pragma unroll
    for (int i = 0; i < 3; i++)
#pragma unroll
        for (int j = 0; j < 3; j++)
#pragma unroll
            for (int k = 0; k < 3; k++)
                m = fmaxf(m, s[i * 100 + j * 10 + k]);

    if (!(m > 0.1f)) {
        size_t sp = ((size_t)b << 22) + ((size_t)(d0 + dz) << 12) + ((h0 + hy) << 6) + (w0 + wx);
#pragma unroll
        for (int c = 0; c < 16; c++)
            out[sp + ((size_t)c << 18)] = 0.f;
    }
}

// ---------------------------------------------------------------------------
extern "C" void kernel_launch(void* const* d_in, const int* in_sizes, int n_in,
                              void* d_out, int out_size)
{
    const float* x   = (const float*)d_in[0];
    const float* rm  = (const float*)d_in[1];
    const float* W1  = (const float*)d_in[2];
    const float* b1  = (const float*)d_in[3];
    const float* W2  = (const float*)d_in[4];
    float* out = (float*)d_out;

    int B = in_sizes[0] >> 22;

    nca_prep<<<1, 256>>>(W1, W2);
    nca_pass1<<<B << 11, 128, SMEM_P1>>>(x, rm, b1, out);
    nca_pass2<<<B << 10, 256>>>(out);
}